// round 2
// baseline (speedup 1.0000x reference)
#include <cuda_runtime.h>
#include <cuda_bf16.h>

// Problem constants
#define NODES     4096      // B*N = 8*512
#define T_HIST    24
#define D_SKIP    256
#define E_END     128
#define KW        13
#define F_STEPS   12
#define OUT_DIM   2
#define NTHREADS  128

// smem layout (floats), total 10592 floats = 42368 bytes (static, <48KB)
//  stage 1: xs [24 x 260]  at 0        (A-frag reads may touch rows 24..31 -> spill into w1s region, harmless garbage, rows discarded)
//           w1s [32 x 136] at 6240
//  stage 2 (after reuse):
//           hs  [24 x 136] at 0        (reuses xs region)
//           w2s [13*2*128=3328] at 6240 (reuses w1s region)
//           red [96]       at 6240+3328=9568
#define XS_STRIDE  260
#define W1S_STRIDE 136
#define HS_STRIDE  136
#define W1S_OFF    6240
#define W2S_OFF    6240
#define RED_OFF    9568
#define SMEM_FLOATS 10592

__device__ __forceinline__ float tf32_rna(float x) {
    unsigned u;
    asm("cvt.rna.tf32.f32 %0, %1;" : "=r"(u) : "f"(x));
    return __uint_as_float(u);
}

__device__ __forceinline__ void mma_tf32(float (&d)[4], const unsigned (&a)[4],
                                         unsigned b0, unsigned b1) {
    asm volatile(
        "mma.sync.aligned.m16n8k8.row.col.f32.tf32.tf32.f32 "
        "{%0,%1,%2,%3}, {%4,%5,%6,%7}, {%8,%9}, {%0,%1,%2,%3};"
        : "+f"(d[0]), "+f"(d[1]), "+f"(d[2]), "+f"(d[3])
        : "r"(a[0]), "r"(a[1]), "r"(a[2]), "r"(a[3]), "r"(b0), "r"(b1));
}

__global__ void __launch_bounds__(NTHREADS)
tcnn_moe_kernel(const float* __restrict__ x,
                const int* __restrict__ labels,
                const float* __restrict__ W1,
                const float* __restrict__ b1,
                const float* __restrict__ W2,
                const float* __restrict__ b2,
                float* __restrict__ out)
{
    __shared__ __align__(16) float sm[SMEM_FLOATS];
    float* xs  = sm;                 // [24][260]
    float* w1s = sm + W1S_OFF;       // [32][136]

    const int node = blockIdx.x;
    const int tid  = threadIdx.x;
    const int warp = tid >> 5;
    const int lane = tid & 31;
    const int g    = lane >> 2;      // groupID 0..7
    const int tig  = lane & 3;       // thread-in-group 0..3

    const int lbl = labels[node];

    // ---- load relu(x) -> tf32 -> xs ----
    const float* xg = x + (size_t)node * (T_HIST * D_SKIP);
    #pragma unroll
    for (int i = tid; i < (T_HIST * D_SKIP) / 4; i += NTHREADS) {
        float4 v = ((const float4*)xg)[i];
        v.x = tf32_rna(fmaxf(v.x, 0.f));
        v.y = tf32_rna(fmaxf(v.y, 0.f));
        v.z = tf32_rna(fmaxf(v.z, 0.f));
        v.w = tf32_rna(fmaxf(v.w, 0.f));
        int off = i * 4;
        int t = off >> 8;         // /256
        int k = off & 255;
        *(float4*)(xs + t * XS_STRIDE + k) = v;
    }

    // ---- stage 1 GEMM: h[t][e] = relu(x)[t][:] . W1[lbl][e][:] ----
    float acc[2][4][4];
    #pragma unroll
    for (int mt = 0; mt < 2; ++mt)
        #pragma unroll
        for (int nt = 0; nt < 4; ++nt)
            #pragma unroll
            for (int i = 0; i < 4; ++i)
                acc[mt][nt][i] = 0.f;

    const float* w1g = W1 + (size_t)lbl * (E_END * D_SKIP) + (size_t)tid * D_SKIP;

    #pragma unroll 1
    for (int c = 0; c < 8; ++c) {        // K chunks of 32
        const int k0 = c * 32;
        __syncthreads();                 // previous chunk consumed (also fences xs on c==0)
        // load W1 chunk transposed: w1s[klocal][e], e = tid
        #pragma unroll
        for (int j = 0; j < 8; ++j) {
            float4 v = *(const float4*)(w1g + k0 + j * 4);
            int kl = j * 4;
            w1s[(kl + 0) * W1S_STRIDE + tid] = tf32_rna(v.x);
            w1s[(kl + 1) * W1S_STRIDE + tid] = tf32_rna(v.y);
            w1s[(kl + 2) * W1S_STRIDE + tid] = tf32_rna(v.z);
            w1s[(kl + 3) * W1S_STRIDE + tid] = tf32_rna(v.w);
        }
        __syncthreads();

        #pragma unroll
        for (int kt = 0; kt < 4; ++kt) {
            const int kb = kt * 8;            // k within chunk
            const int kg = k0 + kb;           // global k (for xs)
            unsigned a[2][4];
            #pragma unroll
            for (int mt = 0; mt < 2; ++mt) {
                const int r0 = mt * 16 + g;
                a[mt][0] = __float_as_uint(xs[r0 * XS_STRIDE + kg + tig]);
                a[mt][1] = __float_as_uint(xs[(r0 + 8) * XS_STRIDE + kg + tig]);
                a[mt][2] = __float_as_uint(xs[r0 * XS_STRIDE + kg + tig + 4]);
                a[mt][3] = __float_as_uint(xs[(r0 + 8) * XS_STRIDE + kg + tig + 4]);
            }
            const int krow0 = (kb + tig) * W1S_STRIDE;
            const int krow1 = (kb + tig + 4) * W1S_STRIDE;
            #pragma unroll
            for (int nt = 0; nt < 4; ++nt) {
                const int col = warp * 32 + nt * 8 + g;
                unsigned bb0 = __float_as_uint(w1s[krow0 + col]);
                unsigned bb1 = __float_as_uint(w1s[krow1 + col]);
                mma_tf32(acc[0][nt], a[0], bb0, bb1);
                mma_tf32(acc[1][nt], a[1], bb0, bb1);
            }
        }
    }

    __syncthreads();   // all xs reads done; safe to overwrite with hs

    // ---- epilogue: h = relu(acc + b1) -> hs (region of xs) ----
    float* hs  = sm;               // [24][136]
    float* w2s = sm + W2S_OFF;     // [13][2][128]
    float* red = sm + RED_OFF;     // [96]

    const float* b1g = b1 + lbl * E_END;
    #pragma unroll
    for (int nt = 0; nt < 4; ++nt) {
        const int col0 = warp * 32 + nt * 8 + 2 * tig;
        const float bx = b1g[col0];
        const float by = b1g[col0 + 1];
        #pragma unroll
        for (int mt = 0; mt < 2; ++mt) {
            const int rlo = mt * 16 + g;        // always < 24
            hs[rlo * HS_STRIDE + col0]     = fmaxf(acc[mt][nt][0] + bx, 0.f);
            hs[rlo * HS_STRIDE + col0 + 1] = fmaxf(acc[mt][nt][1] + by, 0.f);
            const int rhi = rlo + 8;
            if (rhi < T_HIST) {
                hs[rhi * HS_STRIDE + col0]     = fmaxf(acc[mt][nt][2] + bx, 0.f);
                hs[rhi * HS_STRIDE + col0 + 1] = fmaxf(acc[mt][nt][3] + by, 0.f);
            }
        }
    }

    // ---- load W2 (transposed to [kk][o][e]) into w1s region ----
    const float* w2g = W2 + (size_t)lbl * (OUT_DIM * E_END * KW);
    for (int i = tid; i < OUT_DIM * E_END * KW; i += NTHREADS) {
        int o  = i / (E_END * KW);
        int r  = i - o * (E_END * KW);
        int e  = r / KW;
        int kk = r - e * KW;
        w2s[kk * (OUT_DIM * E_END) + o * E_END + e] = w2g[i];
    }
    __syncthreads();

    // ---- stage 2: out[f][o] = sum_{kk,e} hs[f+kk][e] * W2[o][e][kk] + b2[o] ----
    if (tid < 96) {
        const int f  = tid % 12;
        const int o  = (tid / 12) % 2;
        const int eq = tid / 24;       // 0..3, e-chunk of 32
        const int e0 = eq * 32;
        float4 s = make_float4(0.f, 0.f, 0.f, 0.f);
        #pragma unroll
        for (int kk = 0; kk < KW; ++kk) {
            const float4* hp = (const float4*)(hs + (f + kk) * HS_STRIDE + e0);
            const float4* wp = (const float4*)(w2s + kk * (OUT_DIM * E_END) + o * E_END + e0);
            #pragma unroll
            for (int j = 0; j < 8; ++j) {
                float4 hv = hp[j];
                float4 wv = wp[j];
                s.x = fmaf(hv.x, wv.x, s.x);
                s.y = fmaf(hv.y, wv.y, s.y);
                s.z = fmaf(hv.z, wv.z, s.z);
                s.w = fmaf(hv.w, wv.w, s.w);
            }
        }
        red[tid] = (s.x + s.y) + (s.z + s.w);
    }
    __syncthreads();

    if (tid < 24) {
        const int f = tid % 12;
        const int o = tid / 12;
        float sum = red[tid] + red[tid + 24] + red[tid + 48] + red[tid + 72];
        sum += b2[lbl * OUT_DIM + o];
        out[(size_t)node * (F_STEPS * OUT_DIM) + f * OUT_DIM + o] = sum;
    }
}

extern "C" void kernel_launch(void* const* d_in, const int* in_sizes, int n_in,
                              void* d_out, int out_size) {
    const float* x      = (const float*)d_in[0];
    const int*   labels = (const int*)d_in[1];
    const float* W1     = (const float*)d_in[2];
    const float* b1     = (const float*)d_in[3];
    const float* W2     = (const float*)d_in[4];
    const float* b2     = (const float*)d_in[5];
    float* out = (float*)d_out;

    tcnn_moe_kernel<<<NODES, NTHREADS>>>(x, labels, W1, b1, W2, b2, out);
}

// round 3
// speedup vs baseline: 1.2609x; 1.2609x over previous
#include <cuda_runtime.h>
#include <cuda_bf16.h>

// Problem constants
#define NODES     4096      // B*N = 8*512
#define T_HIST    24
#define D_SKIP    256
#define E_END     128
#define KW        13
#define F_STEPS   12
#define OUT_DIM   2
#define NTHREADS  128

// smem layout (floats)
//  stage 1: xs [24 x 260]  at 0   (A-frag reads may touch rows 24..31 -> spill into w1s region, harmless)
//           w1s [32 x 136] at 6240
//  stage 2: hs  [24 x 136] at 0   (reuses xs region)
//           red [4 x 24]   at 6240 (reuses w1s region)
#define XS_STRIDE  260
#define W1S_STRIDE 136
#define HS_STRIDE  136
#define W1S_OFF    6240
#define RED_OFF    6240
#define SMEM_FLOATS 10592

__device__ __forceinline__ float tf32_rna(float x) {
    unsigned u;
    asm("cvt.rna.tf32.f32 %0, %1;" : "=r"(u) : "f"(x));
    return __uint_as_float(u);
}

__device__ __forceinline__ void mma_tf32(float (&d)[4], const unsigned (&a)[4],
                                         unsigned b0, unsigned b1) {
    asm volatile(
        "mma.sync.aligned.m16n8k8.row.col.f32.tf32.tf32.f32 "
        "{%0,%1,%2,%3}, {%4,%5,%6,%7}, {%8,%9}, {%0,%1,%2,%3};"
        : "+f"(d[0]), "+f"(d[1]), "+f"(d[2]), "+f"(d[3])
        : "r"(a[0]), "r"(a[1]), "r"(a[2]), "r"(a[3]), "r"(b0), "r"(b1));
}

__global__ void __launch_bounds__(NTHREADS)
tcnn_moe_kernel(const float* __restrict__ x,
                const int* __restrict__ labels,
                const float* __restrict__ W1,
                const float* __restrict__ b1,
                const float* __restrict__ W2,
                const float* __restrict__ b2,
                float* __restrict__ out)
{
    __shared__ __align__(16) float sm[SMEM_FLOATS];
    float* xs  = sm;                 // [24][260]
    float* w1s = sm + W1S_OFF;       // [32][136]

    const int node = blockIdx.x;
    const int tid  = threadIdx.x;
    const int warp = tid >> 5;
    const int lane = tid & 31;
    const int g    = lane >> 2;      // groupID 0..7
    const int tig  = lane & 3;       // thread-in-group 0..3

    const int lbl = labels[node];

    // ---- load relu(x) -> tf32 -> xs ----
    const float* xg = x + (size_t)node * (T_HIST * D_SKIP);
    #pragma unroll
    for (int i = tid; i < (T_HIST * D_SKIP) / 4; i += NTHREADS) {
        float4 v = ((const float4*)xg)[i];
        v.x = tf32_rna(fmaxf(v.x, 0.f));
        v.y = tf32_rna(fmaxf(v.y, 0.f));
        v.z = tf32_rna(fmaxf(v.z, 0.f));
        v.w = tf32_rna(fmaxf(v.w, 0.f));
        int off = i * 4;
        int t = off >> 8;         // /256
        int k = off & 255;
        *(float4*)(xs + t * XS_STRIDE + k) = v;
    }

    // ---- stage 1 GEMM: h[t][e] = relu(x)[t][:] . W1[lbl][e][:] ----
    float acc[2][4][4];
    #pragma unroll
    for (int mt = 0; mt < 2; ++mt)
        #pragma unroll
        for (int nt = 0; nt < 4; ++nt)
            #pragma unroll
            for (int i = 0; i < 4; ++i)
                acc[mt][nt][i] = 0.f;

    const float* w1g = W1 + (size_t)lbl * (E_END * D_SKIP) + (size_t)tid * D_SKIP;

    #pragma unroll 1
    for (int c = 0; c < 8; ++c) {        // K chunks of 32
        const int k0 = c * 32;
        __syncthreads();                 // previous chunk consumed (also fences xs on c==0)
        // load W1 chunk transposed: w1s[klocal][e], e = tid
        #pragma unroll
        for (int j = 0; j < 8; ++j) {
            float4 v = *(const float4*)(w1g + k0 + j * 4);
            int kl = j * 4;
            w1s[(kl + 0) * W1S_STRIDE + tid] = tf32_rna(v.x);
            w1s[(kl + 1) * W1S_STRIDE + tid] = tf32_rna(v.y);
            w1s[(kl + 2) * W1S_STRIDE + tid] = tf32_rna(v.z);
            w1s[(kl + 3) * W1S_STRIDE + tid] = tf32_rna(v.w);
        }
        __syncthreads();

        #pragma unroll
        for (int kt = 0; kt < 4; ++kt) {
            const int kb = kt * 8;            // k within chunk
            const int kg = k0 + kb;           // global k (for xs)
            unsigned a[2][4];
            #pragma unroll
            for (int mt = 0; mt < 2; ++mt) {
                const int r0 = mt * 16 + g;
                a[mt][0] = __float_as_uint(xs[r0 * XS_STRIDE + kg + tig]);
                a[mt][1] = __float_as_uint(xs[(r0 + 8) * XS_STRIDE + kg + tig]);
                a[mt][2] = __float_as_uint(xs[r0 * XS_STRIDE + kg + tig + 4]);
                a[mt][3] = __float_as_uint(xs[(r0 + 8) * XS_STRIDE + kg + tig + 4]);
            }
            const int krow0 = (kb + tig) * W1S_STRIDE;
            const int krow1 = (kb + tig + 4) * W1S_STRIDE;
            #pragma unroll
            for (int nt = 0; nt < 4; ++nt) {
                const int col = warp * 32 + nt * 8 + g;
                unsigned bb0 = __float_as_uint(w1s[krow0 + col]);
                unsigned bb1 = __float_as_uint(w1s[krow1 + col]);
                mma_tf32(acc[0][nt], a[0], bb0, bb1);
                mma_tf32(acc[1][nt], a[1], bb0, bb1);
            }
        }
    }

    __syncthreads();   // all xs reads done; safe to overwrite with hs

    // ---- epilogue: h = relu(acc + b1) -> hs (region of xs) ----
    float* hs  = sm;               // [24][136]
    float* red = sm + RED_OFF;     // [4][24]

    const float* b1g = b1 + lbl * E_END;
    #pragma unroll
    for (int nt = 0; nt < 4; ++nt) {
        const int col0 = warp * 32 + nt * 8 + 2 * tig;
        const float bx = b1g[col0];
        const float by = b1g[col0 + 1];
        #pragma unroll
        for (int mt = 0; mt < 2; ++mt) {
            const int rlo = mt * 16 + g;        // always < 24
            hs[rlo * HS_STRIDE + col0]     = fmaxf(acc[mt][nt][0] + bx, 0.f);
            hs[rlo * HS_STRIDE + col0 + 1] = fmaxf(acc[mt][nt][1] + by, 0.f);
            const int rhi = rlo + 8;
            if (rhi < T_HIST) {
                hs[rhi * HS_STRIDE + col0]     = fmaxf(acc[mt][nt][2] + bx, 0.f);
                hs[rhi * HS_STRIDE + col0 + 1] = fmaxf(acc[mt][nt][3] + by, 0.f);
            }
        }
    }

    // ---- load this thread's W2 slice into registers (e = tid) ----
    // W2 layout: (E, OUT_DIM, END, KW); w2r[o][kk] = W2[lbl][o][tid][kk]
    const float* w2g = W2 + (size_t)lbl * (OUT_DIM * E_END * KW) + (size_t)tid * KW;
    float w2r[OUT_DIM][KW];
    #pragma unroll
    for (int o = 0; o < OUT_DIM; ++o)
        #pragma unroll
        for (int kk = 0; kk < KW; ++kk)
            w2r[o][kk] = w2g[o * (E_END * KW) + kk];

    __syncthreads();   // hs fully written

    // ---- stage 2: register-resident per-column accumulation ----
    // out[f][o] = sum_e sum_kk h[f+kk][e] * W2[o][e][kk]
    // Thread owns column e=tid: reads h[t][tid] once per t, scatters into (f,o) accs.
    float acc2[F_STEPS][OUT_DIM];
    #pragma unroll
    for (int f = 0; f < F_STEPS; ++f) {
        acc2[f][0] = 0.f;
        acc2[f][1] = 0.f;
    }
    #pragma unroll
    for (int t = 0; t < T_HIST; ++t) {
        const float hv = hs[t * HS_STRIDE + tid];
        const int kklo = (t - (F_STEPS - 1)) > 0 ? (t - (F_STEPS - 1)) : 0;
        const int kkhi = t < (KW - 1) ? t : (KW - 1);
        #pragma unroll
        for (int kk = 0; kk < KW; ++kk) {
            if (kk >= kklo && kk <= kkhi) {      // compile-time per (t,kk)
                const int f = t - kk;
                acc2[f][0] = fmaf(hv, w2r[0][kk], acc2[f][0]);
                acc2[f][1] = fmaf(hv, w2r[1][kk], acc2[f][1]);
            }
        }
    }

    // ---- reduce across the 128 e-columns ----
    // intra-warp butterfly, then cross-warp via tiny smem
    #pragma unroll
    for (int f = 0; f < F_STEPS; ++f) {
        #pragma unroll
        for (int o = 0; o < OUT_DIM; ++o) {
            float v = acc2[f][o];
            v += __shfl_xor_sync(0xffffffffu, v, 16);
            v += __shfl_xor_sync(0xffffffffu, v, 8);
            v += __shfl_xor_sync(0xffffffffu, v, 4);
            v += __shfl_xor_sync(0xffffffffu, v, 2);
            v += __shfl_xor_sync(0xffffffffu, v, 1);
            acc2[f][o] = v;
        }
    }
    if (lane == 0) {
        #pragma unroll
        for (int f = 0; f < F_STEPS; ++f) {
            red[warp * 24 + f * 2 + 0] = acc2[f][0];
            red[warp * 24 + f * 2 + 1] = acc2[f][1];
        }
    }
    __syncthreads();

    if (tid < F_STEPS * OUT_DIM) {
        const int o = tid & 1;
        float sum = red[tid] + red[24 + tid] + red[48 + tid] + red[72 + tid];
        sum += b2[lbl * OUT_DIM + o];
        out[(size_t)node * (F_STEPS * OUT_DIM) + tid] = sum;
    }
}

extern "C" void kernel_launch(void* const* d_in, const int* in_sizes, int n_in,
                              void* d_out, int out_size) {
    const float* x      = (const float*)d_in[0];
    const int*   labels = (const int*)d_in[1];
    const float* W1     = (const float*)d_in[2];
    const float* b1     = (const float*)d_in[3];
    const float* W2     = (const float*)d_in[4];
    const float* b2     = (const float*)d_in[5];
    float* out = (float*)d_out;

    tcnn_moe_kernel<<<NODES, NTHREADS>>>(x, labels, W1, b1, W2, b2, out);
}

// round 4
// speedup vs baseline: 2.6669x; 2.1151x over previous
#include <cuda_runtime.h>
#include <cuda_bf16.h>

// ---- problem constants ----
#define NODES     4096
#define T_HIST    24
#define D_SKIP    256
#define E_END     128
#define KW        13
#define F_STEPS   12
#define OUT_DIM   2

#define NPB       5          // nodes per block
#define NTHREADS  256
#define MAXCTA    832

// smem layout (floats), dynamic
//  xs  [128 rows][132]  @ 0      (rows = node_slot*24 + t; also reused as hs after mainloop)
//  w1s [128 e][36]      @ 16896  (one 32-k chunk, tf32)
//  w2s [13 kk][258]     @ 21504  ([kk][o*128+e], stride 258)
//  red [5][4][24]       @ 24858
#define XS_OFF    0
#define XS_STRIDE 132
#define W1S_OFF   16896
#define W1S_STRIDE 36
#define W2S_OFF   21504
#define W2S_STRIDE 258
#define RED_OFF   24858
#define SMEM_FLOATS 25344
#define SMEM_BYTES  (SMEM_FLOATS * 4)

// ---- device globals (scratch; no allocation allowed) ----
__device__ int d_perm[NODES];
__device__ int d_cta_expert[MAXCTA];
__device__ int d_cta_base[MAXCTA];
__device__ int d_cta_cnt[MAXCTA];
__device__ int d_num_ctas;

__device__ __forceinline__ float tf32_rna(float x) {
    unsigned u;
    asm("cvt.rna.tf32.f32 %0, %1;" : "=r"(u) : "f"(x));
    return __uint_as_float(u);
}

__device__ __forceinline__ void mma_tf32(float (&d)[4], const unsigned (&a)[4],
                                         unsigned b0, unsigned b1) {
    asm volatile(
        "mma.sync.aligned.m16n8k8.row.col.f32.tf32.tf32.f32 "
        "{%0,%1,%2,%3}, {%4,%5,%6,%7}, {%8,%9}, {%0,%1,%2,%3};"
        : "+f"(d[0]), "+f"(d[1]), "+f"(d[2]), "+f"(d[3])
        : "r"(a[0]), "r"(a[1]), "r"(a[2]), "r"(a[3]), "r"(b0), "r"(b1));
}

// ================= prepass: bucket nodes by expert, build CTA table =================
__global__ void prepass_kernel(const int* __restrict__ labels) {
    __shared__ int cnt[8];
    __shared__ int off[9];
    __shared__ int pos[8];
    const int tid = threadIdx.x;
    if (tid < 8) cnt[tid] = 0;
    __syncthreads();
    for (int i = tid; i < NODES; i += blockDim.x) atomicAdd(&cnt[labels[i]], 1);
    __syncthreads();
    if (tid == 0) {
        off[0] = 0;
        for (int e = 0; e < 8; ++e) off[e + 1] = off[e] + cnt[e];
        for (int e = 0; e < 8; ++e) pos[e] = off[e];
    }
    __syncthreads();
    for (int i = tid; i < NODES; i += blockDim.x) {
        int l = labels[i];
        int p = atomicAdd(&pos[l], 1);
        d_perm[p] = i;
    }
    if (tid == 0) {
        int c = 0;
        for (int e = 0; e < 8; ++e) {
            int n = cnt[e], s = off[e];
            for (int j = 0; j < n; j += NPB) {
                d_cta_expert[c] = e;
                d_cta_base[c]   = s + j;
                d_cta_cnt[c]    = (n - j < NPB) ? (n - j) : NPB;
                ++c;
            }
        }
        d_num_ctas = c;
    }
}

// ================= main kernel =================
__global__ void __launch_bounds__(NTHREADS, 2)
tcnn_grouped_kernel(const float* __restrict__ x,
                    const float* __restrict__ W1,
                    const float* __restrict__ b1,
                    const float* __restrict__ W2,
                    const float* __restrict__ b2,
                    float* __restrict__ out)
{
    extern __shared__ __align__(16) float sm[];
    const int bid = blockIdx.x;
    if (bid >= d_num_ctas) return;

    const int expert = d_cta_expert[bid];
    const int base   = d_cta_base[bid];
    const int nm     = d_cta_cnt[bid];

    const int tid  = threadIdx.x;
    const int warp = tid >> 5;
    const int lane = tid & 31;
    const int g    = lane >> 2;
    const int tig  = lane & 3;
    const int wm   = warp & 1;       // 0..1 : e-half (64 each)
    const int wn   = warp >> 1;      // 0..3 : row-quarter (32 each)

    int gn[NPB];
    #pragma unroll
    for (int s = 0; s < NPB; ++s) gn[s] = (s < nm) ? d_perm[base + s] : 0;

    // ---- stage-2 weights into smem (once per CTA, shared by all nodes) ----
    const float* w2g = W2 + (size_t)expert * (OUT_DIM * E_END * KW);
    for (int i = tid; i < OUT_DIM * E_END * KW; i += NTHREADS) {
        int o  = i / (E_END * KW);
        int r  = i - o * (E_END * KW);
        int e  = r / KW;
        int kk = r - e * KW;
        sm[W2S_OFF + kk * W2S_STRIDE + o * E_END + e] = w2g[i];
    }

    // ---- mainloop: D[e][row] = sum_k W1[e][k] * relu(x)[row][k], tf32 mma ----
    float acc[4][4][4];
    #pragma unroll
    for (int mt = 0; mt < 4; ++mt)
        #pragma unroll
        for (int nt = 0; nt < 4; ++nt)
            #pragma unroll
            for (int i = 0; i < 4; ++i) acc[mt][nt][i] = 0.f;

    const float* w1g = W1 + (size_t)expert * (E_END * D_SKIP);
    const int pe = tid >> 3;      // 0..31 (e base for W1 chunk load)
    const int pk = tid & 7;       // 0..7  (k-quad)

    #pragma unroll 1
    for (int half = 0; half < 2; ++half) {
        const int kbase = half * 128;
        __syncthreads();   // xs region free (prev half consumed)

        // load xs: relu+tf32, rows = s*24+t, k-local 0..127
        for (int s = 0; s < nm; ++s) {
            const float* xg = x + (size_t)gn[s] * (T_HIST * D_SKIP) + kbase;
            #pragma unroll
            for (int i = tid; i < T_HIST * 32; i += NTHREADS) {
                int t  = i >> 5;
                int kq = i & 31;
                float4 v = *(const float4*)(xg + t * D_SKIP + kq * 4);
                v.x = tf32_rna(fmaxf(v.x, 0.f));
                v.y = tf32_rna(fmaxf(v.y, 0.f));
                v.z = tf32_rna(fmaxf(v.z, 0.f));
                v.w = tf32_rna(fmaxf(v.w, 0.f));
                *(float4*)(sm + XS_OFF + (s * T_HIST + t) * XS_STRIDE + kq * 4) = v;
            }
        }

        // prefetch W1 chunk 0 of this half
        float4 pre[4];
        #pragma unroll
        for (int j = 0; j < 4; ++j)
            pre[j] = *(const float4*)(w1g + (size_t)(pe + j * 32) * D_SKIP + kbase + pk * 4);

        #pragma unroll 1
        for (int c = 0; c < 4; ++c) {
            __syncthreads();   // w1s free (+ xs ready when c==0)
            // STS prefetched chunk as tf32
            #pragma unroll
            for (int j = 0; j < 4; ++j) {
                float4 v = pre[j];
                v.x = tf32_rna(v.x);
                v.y = tf32_rna(v.y);
                v.z = tf32_rna(v.z);
                v.w = tf32_rna(v.w);
                *(float4*)(sm + W1S_OFF + (pe + j * 32) * W1S_STRIDE + pk * 4) = v;
            }
            if (c < 3) {
                #pragma unroll
                for (int j = 0; j < 4; ++j)
                    pre[j] = *(const float4*)(w1g + (size_t)(pe + j * 32) * D_SKIP + kbase + (c + 1) * 32 + pk * 4);
            }
            __syncthreads();

            #pragma unroll
            for (int kt = 0; kt < 4; ++kt) {
                const int kb = kt * 8;              // k-local within chunk
                const int xk = c * 32 + kb;         // k-local within half (for xs)
                unsigned a[4][4];
                #pragma unroll
                for (int mt = 0; mt < 4; ++mt) {
                    const int e0 = wm * 64 + mt * 16 + g;
                    a[mt][0] = __float_as_uint(sm[W1S_OFF + e0 * W1S_STRIDE + kb + tig]);
                    a[mt][1] = __float_as_uint(sm[W1S_OFF + (e0 + 8) * W1S_STRIDE + kb + tig]);
                    a[mt][2] = __float_as_uint(sm[W1S_OFF + e0 * W1S_STRIDE + kb + tig + 4]);
                    a[mt][3] = __float_as_uint(sm[W1S_OFF + (e0 + 8) * W1S_STRIDE + kb + tig + 4]);
                }
                #pragma unroll
                for (int nt = 0; nt < 4; ++nt) {
                    const int col = wn * 32 + nt * 8 + g;   // row index (B n-dim)
                    unsigned b0 = __float_as_uint(sm[XS_OFF + col * XS_STRIDE + xk + tig]);
                    unsigned b1v = __float_as_uint(sm[XS_OFF + col * XS_STRIDE + xk + tig + 4]);
                    #pragma unroll
                    for (int mt = 0; mt < 4; ++mt)
                        mma_tf32(acc[mt][nt], a[mt], b0, b1v);
                }
            }
        }
    }

    __syncthreads();   // all xs reads done -> reuse region as hs[row][e]

    // ---- epilogue: hs[row][e] = relu(D[e][row] + b1[e]) ----
    const float* b1g = b1 + expert * E_END;
    const int maxrow = nm * T_HIST;
    #pragma unroll
    for (int mt = 0; mt < 4; ++mt) {
        const int eA = wm * 64 + mt * 16 + g;
        const int eB = eA + 8;
        const float bA = b1g[eA];
        const float bB = b1g[eB];
        #pragma unroll
        for (int nt = 0; nt < 4; ++nt) {
            const int row0 = wn * 32 + nt * 8 + 2 * tig;
            if (row0 < maxrow) {
                sm[XS_OFF + row0 * XS_STRIDE + eA] = fmaxf(acc[mt][nt][0] + bA, 0.f);
                sm[XS_OFF + row0 * XS_STRIDE + eB] = fmaxf(acc[mt][nt][2] + bB, 0.f);
            }
            const int row1 = row0 + 1;
            if (row1 < maxrow) {
                sm[XS_OFF + row1 * XS_STRIDE + eA] = fmaxf(acc[mt][nt][1] + bA, 0.f);
                sm[XS_OFF + row1 * XS_STRIDE + eB] = fmaxf(acc[mt][nt][3] + bB, 0.f);
            }
        }
    }
    __syncthreads();

    // ---- stage 2: per-node temporal conv, register resident ----
    // 640 column-jobs max: warp-job wj covers node = wj/4, e-range (wj%4)*32
    #pragma unroll 1
    for (int iter = 0; iter < 3; ++iter) {
        const int wj   = iter * 8 + warp;
        const int node = wj >> 2;
        const int w4   = wj & 3;
        if (node < nm) {
            const int e = w4 * 32 + lane;
            float w2r[OUT_DIM][KW];
            #pragma unroll
            for (int o = 0; o < OUT_DIM; ++o)
                #pragma unroll
                for (int kk = 0; kk < KW; ++kk)
                    w2r[o][kk] = sm[W2S_OFF + kk * W2S_STRIDE + o * E_END + e];

            float a2[F_STEPS][OUT_DIM];
            #pragma unroll
            for (int f = 0; f < F_STEPS; ++f) { a2[f][0] = 0.f; a2[f][1] = 0.f; }

            const float* hsp = sm + XS_OFF + node * T_HIST * XS_STRIDE + e;
            #pragma unroll
            for (int t = 0; t < T_HIST; ++t) {
                const float hv = hsp[t * XS_STRIDE];
                #pragma unroll
                for (int kk = 0; kk < KW; ++kk) {
                    const int f = t - kk;
                    if (f >= 0 && f < F_STEPS) {   // compile-time per (t,kk)
                        a2[f][0] = fmaf(hv, w2r[0][kk], a2[f][0]);
                        a2[f][1] = fmaf(hv, w2r[1][kk], a2[f][1]);
                    }
                }
            }
            #pragma unroll
            for (int f = 0; f < F_STEPS; ++f)
                #pragma unroll
                for (int o = 0; o < OUT_DIM; ++o) {
                    float v = a2[f][o];
                    v += __shfl_xor_sync(0xffffffffu, v, 16);
                    v += __shfl_xor_sync(0xffffffffu, v, 8);
                    v += __shfl_xor_sync(0xffffffffu, v, 4);
                    v += __shfl_xor_sync(0xffffffffu, v, 2);
                    v += __shfl_xor_sync(0xffffffffu, v, 1);
                    a2[f][o] = v;
                }
            if (lane == 0) {
                #pragma unroll
                for (int f = 0; f < F_STEPS; ++f) {
                    sm[RED_OFF + (node * 4 + w4) * 24 + f * 2 + 0] = a2[f][0];
                    sm[RED_OFF + (node * 4 + w4) * 24 + f * 2 + 1] = a2[f][1];
                }
            }
        }
    }
    __syncthreads();

    if (tid < nm * (F_STEPS * OUT_DIM)) {
        const int node = tid / 24;
        const int fo   = tid - node * 24;
        float ssum = sm[RED_OFF + (node * 4 + 0) * 24 + fo]
                   + sm[RED_OFF + (node * 4 + 1) * 24 + fo]
                   + sm[RED_OFF + (node * 4 + 2) * 24 + fo]
                   + sm[RED_OFF + (node * 4 + 3) * 24 + fo];
        ssum += b2[expert * OUT_DIM + (fo & 1)];
        out[(size_t)gn[node] * (F_STEPS * OUT_DIM) + fo] = ssum;
    }
}

extern "C" void kernel_launch(void* const* d_in, const int* in_sizes, int n_in,
                              void* d_out, int out_size) {
    const float* x      = (const float*)d_in[0];
    const int*   labels = (const int*)d_in[1];
    const float* W1     = (const float*)d_in[2];
    const float* b1     = (const float*)d_in[3];
    const float* W2     = (const float*)d_in[4];
    const float* b2     = (const float*)d_in[5];
    float* out = (float*)d_out;

    static bool attr_set = false;
    if (!attr_set) {
        cudaFuncSetAttribute(tcnn_grouped_kernel,
                             cudaFuncAttributeMaxDynamicSharedMemorySize, SMEM_BYTES);
        attr_set = true;
    }

    prepass_kernel<<<1, 512>>>(labels);
    tcnn_grouped_kernel<<<MAXCTA, NTHREADS, SMEM_BYTES>>>(x, W1, b1, W2, b2, out);
}